// round 16
// baseline (speedup 1.0000x reference)
#include <cuda_runtime.h>
#include <cuda_fp16.h>
#include <cstdint>

#define B_ 4
#define T_ 2048
#define C_ 1024
#define H_ 16
#define D_ 64
#define C3_ 3072
#define M_ROWS (B_ * T_)

// ---------------- scratch (device globals: allocation-free) ----------------
__device__ __half g_xhi[(size_t)M_ROWS * C_];
__device__ __half g_wahi[(size_t)C3_ * C_];
__device__ __half g_wphi[(size_t)C_ * C_];
__device__ __half g_qkvh[(size_t)M_ROWS * C3_];
__device__ __half g_yhi[(size_t)M_ROWS * C_];

// ---------------- helpers ----------------
__device__ __forceinline__ uint32_t smem_u32(const void* p) {
    uint32_t a;
    asm("{ .reg .u64 t; cvta.to.shared.u64 t, %1; cvt.u32.u64 %0, t; }"
        : "=r"(a) : "l"(p));
    return a;
}
__device__ __forceinline__ void cp_async16(uint32_t dst, const void* src) {
    asm volatile("cp.async.cg.shared.global [%0], [%1], 16;" :: "r"(dst), "l"(src));
}
__device__ __forceinline__ void cp_commit() {
    asm volatile("cp.async.commit_group;" ::: "memory");
}
__device__ __forceinline__ void cp_wait1() {
    asm volatile("cp.async.wait_group 1;" ::: "memory");
}
__device__ __forceinline__ void cp_wait2() {
    asm volatile("cp.async.wait_group 2;" ::: "memory");
}
__device__ __forceinline__ void ldmx4(uint32_t& r0, uint32_t& r1, uint32_t& r2,
                                      uint32_t& r3, uint32_t addr) {
    asm volatile("ldmatrix.sync.aligned.m8n8.x4.shared.b16 {%0,%1,%2,%3}, [%4];"
                 : "=r"(r0), "=r"(r1), "=r"(r2), "=r"(r3) : "r"(addr));
}
__device__ __forceinline__ void ldmx4t(uint32_t& r0, uint32_t& r1, uint32_t& r2,
                                       uint32_t& r3, uint32_t addr) {
    asm volatile("ldmatrix.sync.aligned.m8n8.x4.trans.shared.b16 {%0,%1,%2,%3}, [%4];"
                 : "=r"(r0), "=r"(r1), "=r"(r2), "=r"(r3) : "r"(addr));
}
__device__ __forceinline__ void mma16816(float& d0, float& d1, float& d2, float& d3,
                                         uint32_t a0, uint32_t a1, uint32_t a2, uint32_t a3,
                                         uint32_t b0, uint32_t b1) {
    asm volatile("mma.sync.aligned.m16n8k16.row.col.f32.f16.f16.f32 "
                 "{%0,%1,%2,%3}, {%4,%5,%6,%7}, {%8,%9}, {%0,%1,%2,%3};"
                 : "+f"(d0), "+f"(d1), "+f"(d2), "+f"(d3)
                 : "r"(a0), "r"(a1), "r"(a2), "r"(a3), "r"(b0), "r"(b1));
}
__device__ __forceinline__ float ex2(float x) {
    float y;
    asm("ex2.approx.ftz.f32 %0, %1;" : "=f"(y) : "f"(x));
    return y;
}
// swizzled byte offset: row-major 128B rows, xor bits 4-6 by row&7
__device__ __forceinline__ uint32_t swz(uint32_t row, uint32_t kb) {
    return row * 128u + (kb ^ ((row & 7u) * 16u));
}

// ---------------- fp32 -> fp16 ----------------
__global__ __launch_bounds__(256)
void trunc_f16(const float4* __restrict__ in, __half2* __restrict__ hi, int n4)
{
    int i = blockIdx.x * 256 + threadIdx.x;
    if (i >= n4) return;
    float4 v = in[i];
    hi[2 * i + 0] = __floats2half2_rn(v.x, v.y);
    hi[2 * i + 1] = __floats2half2_rn(v.z, v.w);
}

// ---------------- mma.sync GEMM: C = Ah @ Wh^T (1-term fp16) ---------------
// CTA tile 128x128, 128 threads (4 warps: 2M x 2N), warp tile 64x64.
// Stage = {A 16KB, B 16KB} = 32KB; 3 stages = 96KB/CTA -> 2 CTAs/SM.
#define TILE_A 16384           // 128 rows x 128B
#define G_STAGE (2 * TILE_A)             // 32KB
#define GEMM_SMEM (3 * G_STAGE)          // 96KB

__global__ __launch_bounds__(128, 2)
void gemm_mma(const __half* __restrict__ Ahi, const __half* __restrict__ Bhi,
              float* __restrict__ Cout, __half* __restrict__ Chi,
              int split_out, int M, int N, int K)
{
    extern __shared__ char smem[];
    const uint32_t sbase = smem_u32(smem);
    const int tid = threadIdx.x;
    const int wid = tid >> 5;
    const int lane = tid & 31;
    const int wm = wid & 1;          // M offset 0/64
    const int wn = wid >> 1;         // N offset 0/64
    const size_t m0 = (size_t)blockIdx.y * 128;
    const size_t n0 = (size_t)blockIdx.x * 128;
    const int quad = lane >> 3;
    const int qr = lane & 7;

    float acc[4][8][4];
#pragma unroll
    for (int i = 0; i < 4; i++)
#pragma unroll
        for (int j = 0; j < 8; j++)
#pragma unroll
            for (int r = 0; r < 4; r++) acc[i][j][r] = 0.f;

    const int NCH = K >> 6;

    auto issue_chunk = [&](int ch, int st) {
        const int k0 = ch * 64;
        char* base = smem + st * G_STAGE;
#pragma unroll
        for (int it = 0; it < 8; it++) {       // A: 1024 16B chunks
            int idx = it * 128 + tid;
            uint32_t row = idx >> 3, c16 = idx & 7;
            uint32_t so = swz(row, c16 * 16u);
            cp_async16(smem_u32(base + so),
                       Ahi + (m0 + row) * (size_t)K + k0 + c16 * 8);
            cp_async16(smem_u32(base + TILE_A + so),
                       Bhi + (n0 + row) * (size_t)K + k0 + c16 * 8);
        }
        cp_commit();
    };

    issue_chunk(0, 0);
    issue_chunk(1, 1);

    for (int ch = 0; ch < NCH; ch++) {
        const int s = ch % 3;
        cp_wait1();            // chunk ch resident (ch+1 may pend)
        __syncthreads();       // all warps done with ch-1 -> stage (ch+2)%3 free
        if (ch + 2 < NCH) issue_chunk(ch + 2, (ch + 2) % 3);
        else cp_commit();

        const uint32_t tA = sbase + s * G_STAGE;
        const uint32_t tB = tA + TILE_A;

#pragma unroll
        for (int kk = 0; kk < 4; kk++) {
            const uint32_t kb = kk * 32;
            uint32_t ah[4][4];
#pragma unroll
            for (int mi = 0; mi < 4; mi++) {
                uint32_t arow = wm * 64 + mi * 16 + (quad & 1) * 8 + qr;
                uint32_t akb = kb + (quad >> 1) * 16;
                ldmx4(ah[mi][0], ah[mi][1], ah[mi][2], ah[mi][3], tA + swz(arow, akb));
            }
            uint32_t bh[8][2];
#pragma unroll
            for (int bi = 0; bi < 4; bi++) {
                uint32_t brow = wn * 64 + bi * 16 + (quad >> 1) * 8 + qr;
                uint32_t bkb = kb + (quad & 1) * 16;
                ldmx4(bh[bi * 2][0], bh[bi * 2][1], bh[bi * 2 + 1][0], bh[bi * 2 + 1][1],
                      tB + swz(brow, bkb));
            }
#pragma unroll
            for (int mi = 0; mi < 4; mi++) {
#pragma unroll
                for (int ni = 0; ni < 8; ni++) {
                    float* d = acc[mi][ni];
                    mma16816(d[0], d[1], d[2], d[3],
                             ah[mi][0], ah[mi][1], ah[mi][2], ah[mi][3],
                             bh[ni][0], bh[ni][1]);
                }
            }
        }
    }

    const int g = lane >> 2;
    const int ti = lane & 3;
#pragma unroll
    for (int mi = 0; mi < 4; mi++) {
#pragma unroll
        for (int ni = 0; ni < 8; ni++) {
            size_t row = m0 + wm * 64 + mi * 16 + g;
            size_t col = n0 + wn * 64 + ni * 8 + 2 * ti;
            float* a = acc[mi][ni];
            if (split_out) {
                *reinterpret_cast<__half2*>(Chi + row * N + col) =
                    __floats2half2_rn(a[0], a[1]);
                *reinterpret_cast<__half2*>(Chi + (row + 8) * N + col) =
                    __floats2half2_rn(a[2], a[3]);
            } else {
                *reinterpret_cast<float2*>(Cout + row * N + col) =
                    make_float2(a[0], a[1]);
                *reinterpret_cast<float2*>(Cout + (row + 8) * N + col) =
                    make_float2(a[2], a[3]);
            }
        }
    }
}

// ---------------- tensor-core flash attention (causal, 1-term fp16) --------
// CTA: 64 q rows, 4 warps x 16 rows, 128 threads. KV tiles of 128, 3-stage.
// SMEM: Qh 8KB + 3 x 32KB KV = 104KB -> 2 CTAs/SM. Single barrier/tile.
// S = Qh Kh^T ; O += Ph Vh   (fp32 accumulate throughout)
#define AT_TILE 16384         // 128 rows x 128B
#define AT_STAGE (2 * AT_TILE)
#define AT_QB 8192
#define AT_SMEM (AT_QB + 3 * AT_STAGE)
#define SCALE_LOG2E 0.1803368801111204f   // (1/8) * log2(e)

__global__ __launch_bounds__(128, 2)
void flash_attn_mma(const __half* __restrict__ qh, __half* __restrict__ yh)
{
    extern __shared__ char smem[];
    const uint32_t sbase = smem_u32(smem);
    const int tid = threadIdx.x;
    const int wid = tid >> 5;
    const int lane = tid & 31;
    const int quad = lane >> 3;
    const int qr = lane & 7;
    const int b = blockIdx.z;
    const int h = blockIdx.y;
    const int qt = gridDim.x - 1 - blockIdx.x;
    const int q0 = qt * 64;
    const int nt = (qt + 2) >> 1;      // KV tiles of 128 covering q0+64 keys

    const size_t bbase = (size_t)(b * T_) * C3_;
    const __half* qsh = qh + bbase + h * D_;
    const __half* ksh = qh + bbase + C_ + h * D_;
    const __half* vsh = qh + bbase + 2 * C_ + h * D_;

    auto issue_kv = [&](int t, int stage) {
        const int j0 = t * 128;
        const uint32_t kvb = sbase + AT_QB + stage * AT_STAGE;
#pragma unroll
        for (int it = 0; it < 8; it++) {
            int idx = it * 128 + tid;               // 1024 chunks per tile
            uint32_t r = idx >> 3, c16 = idx & 7;
            size_t off = (size_t)(j0 + r) * C3_ + c16 * 8;
            uint32_t so = swz(r, c16 * 16u);
            cp_async16(kvb + 0 * AT_TILE + so, ksh + off);
            cp_async16(kvb + 1 * AT_TILE + so, vsh + off);
        }
        cp_commit();
    };

    // group 0: Qh (64 rows x 8 chunks = 512)
#pragma unroll
    for (int it = 0; it < 4; it++) {
        int idx = it * 128 + tid;
        uint32_t r = idx >> 3, c16 = idx & 7;
        cp_async16(sbase + swz(r, c16 * 16u), qsh + (size_t)(q0 + r) * C3_ + c16 * 8);
    }
    cp_commit();
    issue_kv(0, 0);
    if (nt > 1) issue_kv(1, 1); else cp_commit();
    cp_wait2();       // Q resident (2 kv groups may pend)
    __syncthreads();

    uint32_t Qh[4][4];
#pragma unroll
    for (int kf = 0; kf < 4; kf++) {
        uint32_t arow = wid * 16 + (quad & 1) * 8 + qr;
        uint32_t akb = kf * 32 + (quad >> 1) * 16;
        ldmx4(Qh[kf][0], Qh[kf][1], Qh[kf][2], Qh[kf][3], sbase + swz(arow, akb));
    }

    float O[8][4];
#pragma unroll
    for (int i = 0; i < 8; i++)
#pragma unroll
        for (int r = 0; r < 4; r++) O[i][r] = 0.f;
    float m0r = -1e30f, m1r = -1e30f, l0r = 0.f, l1r = 0.f;
    const int row_lo = q0 + wid * 16 + (lane >> 2);

    for (int t = 0; t < nt; t++) {
        const int s = t % 3;
        cp_wait1();            // kv tile t resident (1 newer may pend)
        __syncthreads();       // stage (t+2)%3 free (all warps done with t-1)
        if (t + 2 < nt) issue_kv(t + 2, (t + 2) % 3);
        else cp_commit();

        const int j0 = t * 128;
        const uint32_t stage = sbase + AT_QB + s * AT_STAGE;
        const uint32_t tKh = stage + 0 * AT_TILE;
        const uint32_t tVh = stage + 1 * AT_TILE;

        // ---- S = Qh Kh^T  (64 x 128) ----
        float S[16][4];
#pragma unroll
        for (int i = 0; i < 16; i++)
#pragma unroll
            for (int r = 0; r < 4; r++) S[i][r] = 0.f;

#pragma unroll
        for (int kf = 0; kf < 4; kf++) {
            uint32_t bh[16][2];
#pragma unroll
            for (int bi = 0; bi < 8; bi++) {
                uint32_t brow = bi * 16 + (quad >> 1) * 8 + qr;
                uint32_t bkb = kf * 32 + (quad & 1) * 16;
                ldmx4(bh[bi * 2][0], bh[bi * 2][1], bh[bi * 2 + 1][0], bh[bi * 2 + 1][1],
                      tKh + swz(brow, bkb));
            }
#pragma unroll
            for (int nf = 0; nf < 16; nf++) {
                mma16816(S[nf][0], S[nf][1], S[nf][2], S[nf][3],
                         Qh[kf][0], Qh[kf][1], Qh[kf][2], Qh[kf][3],
                         bh[nf][0], bh[nf][1]);
            }
        }

        // scale + causal mask
#pragma unroll
        for (int nf = 0; nf < 16; nf++)
#pragma unroll
            for (int r = 0; r < 4; r++) S[nf][r] *= SCALE_LOG2E;

        if (j0 + 127 > q0 + wid * 16) {
            const int kvb = j0 + 2 * (lane & 3);
#pragma unroll
            for (int nf = 0; nf < 16; nf++) {
                const int kv = kvb + nf * 8;
                if (kv     > row_lo)     S[nf][0] = -1e30f;
                if (kv + 1 > row_lo)     S[nf][1] = -1e30f;
                if (kv     > row_lo + 8) S[nf][2] = -1e30f;
                if (kv + 1 > row_lo + 8) S[nf][3] = -1e30f;
            }
        }

        // row max
        float rm0 = -1e30f, rm1 = -1e30f;
#pragma unroll
        for (int nf = 0; nf < 16; nf++) {
            rm0 = fmaxf(rm0, fmaxf(S[nf][0], S[nf][1]));
            rm1 = fmaxf(rm1, fmaxf(S[nf][2], S[nf][3]));
        }
        rm0 = fmaxf(rm0, __shfl_xor_sync(0xffffffffu, rm0, 1));
        rm0 = fmaxf(rm0, __shfl_xor_sync(0xffffffffu, rm0, 2));
        rm1 = fmaxf(rm1, __shfl_xor_sync(0xffffffffu, rm1, 1));
        rm1 = fmaxf(rm1, __shfl_xor_sync(0xffffffffu, rm1, 2));

        const float mn0 = fmaxf(m0r, rm0);
        const float mn1 = fmaxf(m1r, rm1);
        const float cr0 = ex2(m0r - mn0);
        const float cr1 = ex2(m1r - mn1);
        m0r = mn0; m1r = mn1;

        float rs0 = 0.f, rs1 = 0.f;
#pragma unroll
        for (int nf = 0; nf < 16; nf++) {
            S[nf][0] = ex2(S[nf][0] - mn0);
            S[nf][1] = ex2(S[nf][1] - mn0);
            S[nf][2] = ex2(S[nf][2] - mn1);
            S[nf][3] = ex2(S[nf][3] - mn1);
            rs0 += S[nf][0] + S[nf][1];
            rs1 += S[nf][2] + S[nf][3];
        }
        rs0 += __shfl_xor_sync(0xffffffffu, rs0, 1);
        rs0 += __shfl_xor_sync(0xffffffffu, rs0, 2);
        rs1 += __shfl_xor_sync(0xffffffffu, rs1, 1);
        rs1 += __shfl_xor_sync(0xffffffffu, rs1, 2);
        l0r = l0r * cr0 + rs0;
        l1r = l1r * cr1 + rs1;

#pragma unroll
        for (int nf = 0; nf < 8; nf++) {
            O[nf][0] *= cr0; O[nf][1] *= cr0;
            O[nf][2] *= cr1; O[nf][3] *= cr1;
        }

        // ---- O += Ph Vh  (128 keys -> 8 kf groups) ----
#pragma unroll
        for (int kf = 0; kf < 8; kf++) {
            uint32_t pah[4];
#pragma unroll
            for (int half = 0; half < 2; half++) {
                __half2 t01 = __floats2half2_rn(S[2 * kf + half][0], S[2 * kf + half][1]);
                __half2 t23 = __floats2half2_rn(S[2 * kf + half][2], S[2 * kf + half][3]);
                pah[2 * half + 0] = *reinterpret_cast<uint32_t*>(&t01);
                pah[2 * half + 1] = *reinterpret_cast<uint32_t*>(&t23);
            }
            uint32_t vh[8][2];
#pragma unroll
            for (int bi = 0; bi < 4; bi++) {
                uint32_t vrow = kf * 16 + (quad & 1) * 8 + qr;
                uint32_t vcb = bi * 32 + (quad >> 1) * 16;
                ldmx4t(vh[bi * 2][0], vh[bi * 2][1], vh[bi * 2 + 1][0],
                       vh[bi * 2 + 1][1], tVh + swz(vrow, vcb));
            }
#pragma unroll
            for (int nf = 0; nf < 8; nf++) {
                mma16816(O[nf][0], O[nf][1], O[nf][2], O[nf][3],
                         pah[0], pah[1], pah[2], pah[3], vh[nf][0], vh[nf][1]);
            }
        }
    }

    // ---- epilogue: normalize, store fp16 ----
    const float li0 = 1.f / l0r;
    const float li1 = 1.f / l1r;
    const size_t r0 = (size_t)(b * T_) + row_lo;
    const int colb = h * D_ + 2 * (lane & 3);
#pragma unroll
    for (int nf = 0; nf < 8; nf++) {
        const size_t c = colb + nf * 8;
        *reinterpret_cast<__half2*>(yh + r0 * C_ + c) =
            __floats2half2_rn(O[nf][0] * li0, O[nf][1] * li0);
        *reinterpret_cast<__half2*>(yh + (r0 + 8) * C_ + c) =
            __floats2half2_rn(O[nf][2] * li1, O[nf][3] * li1);
    }
}

// ---------------- launch ----------------
extern "C" void kernel_launch(void* const* d_in, const int* in_sizes, int n_in,
                              void* d_out, int out_size)
{
    const float* x      = (const float*)d_in[0];
    const float* w_attn = (const float*)d_in[1];
    const float* w_proj = (const float*)d_in[2];
    float* out = (float*)d_out;

    __half *xhi, *wahi, *wphi, *qkvh, *yhi;
    cudaGetSymbolAddress((void**)&xhi, g_xhi);
    cudaGetSymbolAddress((void**)&wahi, g_wahi);
    cudaGetSymbolAddress((void**)&wphi, g_wphi);
    cudaGetSymbolAddress((void**)&qkvh, g_qkvh);
    cudaGetSymbolAddress((void**)&yhi, g_yhi);

    cudaFuncSetAttribute(gemm_mma, cudaFuncAttributeMaxDynamicSharedMemorySize, GEMM_SMEM);
    cudaFuncSetAttribute(flash_attn_mma, cudaFuncAttributeMaxDynamicSharedMemorySize, AT_SMEM);

    {
        int n4 = M_ROWS * C_ / 4;
        trunc_f16<<<(n4 + 255) / 256, 256>>>((const float4*)x, (__half2*)xhi, n4);
    }
    {
        int n4 = C3_ * C_ / 4;
        trunc_f16<<<(n4 + 255) / 256, 256>>>((const float4*)w_attn, (__half2*)wahi, n4);
    }
    {
        int n4 = C_ * C_ / 4;
        trunc_f16<<<(n4 + 255) / 256, 256>>>((const float4*)w_proj, (__half2*)wphi, n4);
    }

    // 1) QKV = xh @ wah^T (1-term fp16) -> fp16
    {
        dim3 g(C3_ / 128, M_ROWS / 128);
        gemm_mma<<<g, 128, GEMM_SMEM>>>(xhi, wahi, nullptr, qkvh, 1, M_ROWS, C3_, C_);
    }
    // 2) tensor-core flash attention (1-term fp16, KV tiles of 128) -> fp16
    {
        dim3 g(T_ / 64, H_, B_);
        flash_attn_mma<<<g, 128, AT_SMEM>>>(qkvh, yhi);
    }
    // 3) out = yh @ wph^T (1-term fp16, fp32 out)
    {
        dim3 g(C_ / 128, M_ROWS / 128);
        gemm_mma<<<g, 128, GEMM_SMEM>>>(yhi, wphi, out, nullptr, 0, M_ROWS, C_, C_);
    }
}

// round 17
// speedup vs baseline: 1.0235x; 1.0235x over previous
#include <cuda_runtime.h>
#include <cuda_fp16.h>
#include <cstdint>

#define B_ 4
#define T_ 2048
#define C_ 1024
#define H_ 16
#define D_ 64
#define C3_ 3072
#define M_ROWS (B_ * T_)

// ---------------- scratch (device globals: allocation-free) ----------------
__device__ __half g_xhi[(size_t)M_ROWS * C_];
__device__ __half g_wahi[(size_t)C3_ * C_];
__device__ __half g_wphi[(size_t)C_ * C_];
__device__ __half g_qkvh[(size_t)M_ROWS * C3_];
__device__ __half g_yhi[(size_t)M_ROWS * C_];

// ---------------- helpers ----------------
__device__ __forceinline__ uint32_t smem_u32(const void* p) {
    uint32_t a;
    asm("{ .reg .u64 t; cvta.to.shared.u64 t, %1; cvt.u32.u64 %0, t; }"
        : "=r"(a) : "l"(p));
    return a;
}
__device__ __forceinline__ void cp_async16(uint32_t dst, const void* src) {
    asm volatile("cp.async.cg.shared.global [%0], [%1], 16;" :: "r"(dst), "l"(src));
}
__device__ __forceinline__ void cp_commit() {
    asm volatile("cp.async.commit_group;" ::: "memory");
}
__device__ __forceinline__ void cp_wait2() {
    asm volatile("cp.async.wait_group 2;" ::: "memory");
}
__device__ __forceinline__ void cp_wait3() {
    asm volatile("cp.async.wait_group 3;" ::: "memory");
}
__device__ __forceinline__ void ldmx4(uint32_t& r0, uint32_t& r1, uint32_t& r2,
                                      uint32_t& r3, uint32_t addr) {
    asm volatile("ldmatrix.sync.aligned.m8n8.x4.shared.b16 {%0,%1,%2,%3}, [%4];"
                 : "=r"(r0), "=r"(r1), "=r"(r2), "=r"(r3) : "r"(addr));
}
__device__ __forceinline__ void ldmx4t(uint32_t& r0, uint32_t& r1, uint32_t& r2,
                                       uint32_t& r3, uint32_t addr) {
    asm volatile("ldmatrix.sync.aligned.m8n8.x4.trans.shared.b16 {%0,%1,%2,%3}, [%4];"
                 : "=r"(r0), "=r"(r1), "=r"(r2), "=r"(r3) : "r"(addr));
}
__device__ __forceinline__ void mma16816(float& d0, float& d1, float& d2, float& d3,
                                         uint32_t a0, uint32_t a1, uint32_t a2, uint32_t a3,
                                         uint32_t b0, uint32_t b1) {
    asm volatile("mma.sync.aligned.m16n8k16.row.col.f32.f16.f16.f32 "
                 "{%0,%1,%2,%3}, {%4,%5,%6,%7}, {%8,%9}, {%0,%1,%2,%3};"
                 : "+f"(d0), "+f"(d1), "+f"(d2), "+f"(d3)
                 : "r"(a0), "r"(a1), "r"(a2), "r"(a3), "r"(b0), "r"(b1));
}
__device__ __forceinline__ float ex2(float x) {
    float y;
    asm("ex2.approx.ftz.f32 %0, %1;" : "=f"(y) : "f"(x));
    return y;
}
// swizzled byte offset: row-major 128B rows, xor bits 4-6 by row&7
__device__ __forceinline__ uint32_t swz(uint32_t row, uint32_t kb) {
    return row * 128u + (kb ^ ((row & 7u) * 16u));
}

// ---------------- fp32 -> fp16 ----------------
__global__ __launch_bounds__(256)
void trunc_f16(const float4* __restrict__ in, __half2* __restrict__ hi, int n4)
{
    int i = blockIdx.x * 256 + threadIdx.x;
    if (i >= n4) return;
    float4 v = in[i];
    hi[2 * i + 0] = __floats2half2_rn(v.x, v.y);
    hi[2 * i + 1] = __floats2half2_rn(v.z, v.w);
}

// ---------------- mma.sync GEMM: C = Ah @ Wh^T (1-term fp16, 4-stage) ------
// Tile 128x64 per CTA, 128 threads (4 warps: 2M x 2N, warp 64x32).
// Stage = {A 16KB, B 8KB} = 24KB; 4 stages = 96KB/CTA -> 2 CTAs/SM.
// Fragment loads double-buffered: kk+1 LDSMs issue before kk's MMAs.
#define TILE_A 16384           // 128 rows x 128B
#define TILE_BB 8192           // 64 rows x 128B
#define G_STAGE (TILE_A + TILE_BB)       // 24KB
#define GEMM_SMEM (4 * G_STAGE)          // 96KB

__global__ __launch_bounds__(128, 2)
void gemm_mma(const __half* __restrict__ Ahi, const __half* __restrict__ Bhi,
              float* __restrict__ Cout, __half* __restrict__ Chi,
              int split_out, int M, int N, int K)
{
    extern __shared__ char smem[];
    const uint32_t sbase = smem_u32(smem);
    const int tid = threadIdx.x;
    const int wid = tid >> 5;
    const int lane = tid & 31;
    const int wm = wid & 1;          // M offset 0/64
    const int wn = wid >> 1;         // N offset 0/32
    const size_t m0 = (size_t)blockIdx.y * 128;
    const size_t n0 = (size_t)blockIdx.x * 64;
    const int quad = lane >> 3;
    const int qr = lane & 7;

    float acc[4][4][4];
#pragma unroll
    for (int i = 0; i < 4; i++)
#pragma unroll
        for (int j = 0; j < 4; j++)
#pragma unroll
            for (int r = 0; r < 4; r++) acc[i][j][r] = 0.f;

    const int NCH = K >> 6;

    auto issue_chunk = [&](int ch, int st) {
        const int k0 = ch * 64;
        char* base = smem + st * G_STAGE;
#pragma unroll
        for (int it = 0; it < 8; it++) {       // A: 1024 16B chunks
            int idx = it * 128 + tid;
            uint32_t row = idx >> 3, c16 = idx & 7;
            cp_async16(smem_u32(base + swz(row, c16 * 16u)),
                       Ahi + (m0 + row) * (size_t)K + k0 + c16 * 8);
        }
#pragma unroll
        for (int it = 0; it < 4; it++) {       // B: 512 chunks
            int idx = it * 128 + tid;
            uint32_t row = idx >> 3, c16 = idx & 7;
            cp_async16(smem_u32(base + TILE_A + swz(row, c16 * 16u)),
                       Bhi + (n0 + row) * (size_t)K + k0 + c16 * 8);
        }
        cp_commit();
    };

    issue_chunk(0, 0);
    issue_chunk(1, 1);
    issue_chunk(2, 2);

    // precomputed lane-invariant fragment addresses (kb added per kk)
    const uint32_t a_row = wm * 64 + (quad & 1) * 8 + qr;
    const uint32_t a_kb0 = (quad >> 1) * 16;
    const uint32_t b_row = wn * 32 + (quad >> 1) * 8 + qr;
    const uint32_t b_kb0 = (quad & 1) * 16;

    for (int ch = 0; ch < NCH; ch++) {
        const int s = ch & 3;
        cp_wait2();            // chunk ch resident (ch+1, ch+2 may pend)
        __syncthreads();       // all warps done with ch-1 -> stage (ch+3)&3 free
        if (ch + 3 < NCH) issue_chunk(ch + 3, (ch + 3) & 3);
        else cp_commit();

        const uint32_t tA = sbase + s * G_STAGE;
        const uint32_t tB = tA + TILE_A;

        uint32_t ah[2][4][4], bh[2][4][2];
        auto ldfr = [&](int kk, int bf) {
            const uint32_t kb = kk * 32;
#pragma unroll
            for (int mi = 0; mi < 4; mi++)
                ldmx4(ah[bf][mi][0], ah[bf][mi][1], ah[bf][mi][2], ah[bf][mi][3],
                      tA + swz(a_row + mi * 16, kb + a_kb0));
#pragma unroll
            for (int bi = 0; bi < 2; bi++)
                ldmx4(bh[bf][bi * 2][0], bh[bf][bi * 2][1],
                      bh[bf][bi * 2 + 1][0], bh[bf][bi * 2 + 1][1],
                      tB + swz(b_row + bi * 16, kb + b_kb0));
        };

        ldfr(0, 0);
#pragma unroll
        for (int kk = 0; kk < 4; kk++) {
            const int cur = kk & 1;
            if (kk < 3) ldfr(kk + 1, cur ^ 1);
#pragma unroll
            for (int mi = 0; mi < 4; mi++) {
#pragma unroll
                for (int ni = 0; ni < 4; ni++) {
                    float* d = acc[mi][ni];
                    mma16816(d[0], d[1], d[2], d[3],
                             ah[cur][mi][0], ah[cur][mi][1], ah[cur][mi][2], ah[cur][mi][3],
                             bh[cur][ni][0], bh[cur][ni][1]);
                }
            }
        }
    }

    const int g = lane >> 2;
    const int ti = lane & 3;
#pragma unroll
    for (int mi = 0; mi < 4; mi++) {
#pragma unroll
        for (int ni = 0; ni < 4; ni++) {
            size_t row = m0 + wm * 64 + mi * 16 + g;
            size_t col = n0 + wn * 32 + ni * 8 + 2 * ti;
            float* a = acc[mi][ni];
            if (split_out) {
                *reinterpret_cast<__half2*>(Chi + row * N + col) =
                    __floats2half2_rn(a[0], a[1]);
                *reinterpret_cast<__half2*>(Chi + (row + 8) * N + col) =
                    __floats2half2_rn(a[2], a[3]);
            } else {
                *reinterpret_cast<float2*>(Cout + row * N + col) =
                    make_float2(a[0], a[1]);
                *reinterpret_cast<float2*>(Cout + (row + 8) * N + col) =
                    make_float2(a[2], a[3]);
            }
        }
    }
}

// ---------------- tensor-core flash attention (causal, 1-term fp16) --------
// CTA: 64 q rows, 4 warps x 16 rows, 128 threads. KV tiles of 64, 4-stage.
// SMEM: Qh 8KB + 4 x 16KB KV = 72KB -> 2 CTAs/SM. Single barrier/tile.
// S = Qh Kh^T ; O += Ph Vh   (fp32 accumulate); K/V frags double-buffered.
#define AT_TILE 8192          // 64 rows x 128B
#define AT_STAGE (2 * AT_TILE)
#define AT_QB 8192
#define AT_SMEM (AT_QB + 4 * AT_STAGE)
#define SCALE_LOG2E 0.1803368801111204f   // (1/8) * log2(e)

__global__ __launch_bounds__(128, 2)
void flash_attn_mma(const __half* __restrict__ qh, __half* __restrict__ yh)
{
    extern __shared__ char smem[];
    const uint32_t sbase = smem_u32(smem);
    const int tid = threadIdx.x;
    const int wid = tid >> 5;
    const int lane = tid & 31;
    const int quad = lane >> 3;
    const int qr = lane & 7;
    const int b = blockIdx.z;
    const int h = blockIdx.y;
    const int qt = gridDim.x - 1 - blockIdx.x;
    const int q0 = qt * 64;
    const int nt = qt + 1;

    const size_t bbase = (size_t)(b * T_) * C3_;
    const __half* qsh = qh + bbase + h * D_;
    const __half* ksh = qh + bbase + C_ + h * D_;
    const __half* vsh = qh + bbase + 2 * C_ + h * D_;

    auto issue_kv = [&](int t, int stage) {
        const int j0 = t * 64;
        const uint32_t kvb = sbase + AT_QB + stage * AT_STAGE;
#pragma unroll
        for (int it = 0; it < 4; it++) {
            int idx = it * 128 + tid;               // 512 chunks per tile
            uint32_t r = idx >> 3, c16 = idx & 7;
            size_t off = (size_t)(j0 + r) * C3_ + c16 * 8;
            uint32_t so = swz(r, c16 * 16u);
            cp_async16(kvb + 0 * AT_TILE + so, ksh + off);
            cp_async16(kvb + 1 * AT_TILE + so, vsh + off);
        }
        cp_commit();
    };

    // group 0: Qh (64 rows x 8 chunks = 512)
#pragma unroll
    for (int it = 0; it < 4; it++) {
        int idx = it * 128 + tid;
        uint32_t r = idx >> 3, c16 = idx & 7;
        cp_async16(sbase + swz(r, c16 * 16u), qsh + (size_t)(q0 + r) * C3_ + c16 * 8);
    }
    cp_commit();
    issue_kv(0, 0);
    if (nt > 1) issue_kv(1, 1); else cp_commit();
    if (nt > 2) issue_kv(2, 2); else cp_commit();
    cp_wait3();       // Q resident (3 kv groups may pend)
    __syncthreads();

    uint32_t Qh[4][4];
#pragma unroll
    for (int kf = 0; kf < 4; kf++) {
        uint32_t arow = wid * 16 + (quad & 1) * 8 + qr;
        uint32_t akb = kf * 32 + (quad >> 1) * 16;
        ldmx4(Qh[kf][0], Qh[kf][1], Qh[kf][2], Qh[kf][3], sbase + swz(arow, akb));
    }

    float O[8][4];
#pragma unroll
    for (int i = 0; i < 8; i++)
#pragma unroll
        for (int r = 0; r < 4; r++) O[i][r] = 0.f;
    float m0r = -1e30f, m1r = -1e30f, l0r = 0.f, l1r = 0.f;
    const int row_lo = q0 + wid * 16 + (lane >> 2);

    const uint32_t k_row = (quad >> 1) * 8 + qr;
    const uint32_t k_kb0 = (quad & 1) * 16;
    const uint32_t v_row = (quad & 1) * 8 + qr;
    const uint32_t v_cb0 = (quad >> 1) * 16;

    for (int t = 0; t < nt; t++) {
        const int s = t & 3;
        cp_wait2();            // kv tile t resident (2 newer may pend)
        __syncthreads();       // stage (t+3)&3 free (all warps done with t-1)
        if (t + 3 < nt) issue_kv(t + 3, (t + 3) & 3);
        else cp_commit();

        const int j0 = t * 64;
        const uint32_t stage = sbase + AT_QB + s * AT_STAGE;
        const uint32_t tKh = stage + 0 * AT_TILE;
        const uint32_t tVh = stage + 1 * AT_TILE;

        // ---- S = Qh Kh^T (K frags double-buffered over kf) ----
        float S[8][4];
#pragma unroll
        for (int i = 0; i < 8; i++)
#pragma unroll
            for (int r = 0; r < 4; r++) S[i][r] = 0.f;

        uint32_t bh[2][8][2];
        auto ldk = [&](int kf, int bf) {
            const uint32_t kb = kf * 32 + k_kb0;
#pragma unroll
            for (int bi = 0; bi < 4; bi++)
                ldmx4(bh[bf][bi * 2][0], bh[bf][bi * 2][1],
                      bh[bf][bi * 2 + 1][0], bh[bf][bi * 2 + 1][1],
                      tKh + swz(k_row + bi * 16, kb));
        };

        ldk(0, 0);
#pragma unroll
        for (int kf = 0; kf < 4; kf++) {
            const int cur = kf & 1;
            if (kf < 3) ldk(kf + 1, cur ^ 1);
#pragma unroll
            for (int nf = 0; nf < 8; nf++) {
                mma16816(S[nf][0], S[nf][1], S[nf][2], S[nf][3],
                         Qh[kf][0], Qh[kf][1], Qh[kf][2], Qh[kf][3],
                         bh[cur][nf][0], bh[cur][nf][1]);
            }
        }

        // scale + causal mask
#pragma unroll
        for (int nf = 0; nf < 8; nf++)
#pragma unroll
            for (int r = 0; r < 4; r++) S[nf][r] *= SCALE_LOG2E;

        if (j0 + 63 > q0 + wid * 16) {
            const int kvb = j0 + 2 * (lane & 3);
#pragma unroll
            for (int nf = 0; nf < 8; nf++) {
                const int kv = kvb + nf * 8;
                if (kv     > row_lo)     S[nf][0] = -1e30f;
                if (kv + 1 > row_lo)     S[nf][1] = -1e30f;
                if (kv     > row_lo + 8) S[nf][2] = -1e30f;
                if (kv + 1 > row_lo + 8) S[nf][3] = -1e30f;
            }
        }

        // row max
        float rm0 = -1e30f, rm1 = -1e30f;
#pragma unroll
        for (int nf = 0; nf < 8; nf++) {
            rm0 = fmaxf(rm0, fmaxf(S[nf][0], S[nf][1]));
            rm1 = fmaxf(rm1, fmaxf(S[nf][2], S[nf][3]));
        }
        rm0 = fmaxf(rm0, __shfl_xor_sync(0xffffffffu, rm0, 1));
        rm0 = fmaxf(rm0, __shfl_xor_sync(0xffffffffu, rm0, 2));
        rm1 = fmaxf(rm1, __shfl_xor_sync(0xffffffffu, rm1, 1));
        rm1 = fmaxf(rm1, __shfl_xor_sync(0xffffffffu, rm1, 2));

        const float mn0 = fmaxf(m0r, rm0);
        const float mn1 = fmaxf(m1r, rm1);
        const float cr0 = ex2(m0r - mn0);
        const float cr1 = ex2(m1r - mn1);
        m0r = mn0; m1r = mn1;

        float rs0 = 0.f, rs1 = 0.f;
#pragma unroll
        for (int nf = 0; nf < 8; nf++) {
            S[nf][0] = ex2(S[nf][0] - mn0);
            S[nf][1] = ex2(S[nf][1] - mn0);
            S[nf][2] = ex2(S[nf][2] - mn1);
            S[nf][3] = ex2(S[nf][3] - mn1);
            rs0 += S[nf][0] + S[nf][1];
            rs1 += S[nf][2] + S[nf][3];
        }
        rs0 += __shfl_xor_sync(0xffffffffu, rs0, 1);
        rs0 += __shfl_xor_sync(0xffffffffu, rs0, 2);
        rs1 += __shfl_xor_sync(0xffffffffu, rs1, 1);
        rs1 += __shfl_xor_sync(0xffffffffu, rs1, 2);
        l0r = l0r * cr0 + rs0;
        l1r = l1r * cr1 + rs1;

#pragma unroll
        for (int nf = 0; nf < 8; nf++) {
            O[nf][0] *= cr0; O[nf][1] *= cr0;
            O[nf][2] *= cr1; O[nf][3] *= cr1;
        }

        // ---- O += Ph Vh (V frags double-buffered over kf) ----
        uint32_t vh[2][8][2];
        auto ldv = [&](int kf, int bf) {
            const uint32_t vr = kf * 16 + v_row;
#pragma unroll
            for (int bi = 0; bi < 4; bi++)
                ldmx4t(vh[bf][bi * 2][0], vh[bf][bi * 2][1],
                       vh[bf][bi * 2 + 1][0], vh[bf][bi * 2 + 1][1],
                       tVh + swz(vr, bi * 32 + v_cb0));
        };

        ldv(0, 0);
#pragma unroll
        for (int kf = 0; kf < 4; kf++) {
            const int cur = kf & 1;
            if (kf < 3) ldv(kf + 1, cur ^ 1);
            uint32_t pah[4];
#pragma unroll
            for (int half = 0; half < 2; half++) {
                __half2 t01 = __floats2half2_rn(S[2 * kf + half][0], S[2 * kf + half][1]);
                __half2 t23 = __floats2half2_rn(S[2 * kf + half][2], S[2 * kf + half][3]);
                pah[2 * half + 0] = *reinterpret_cast<uint32_t*>(&t01);
                pah[2 * half + 1] = *reinterpret_cast<uint32_t*>(&t23);
            }
#pragma unroll
            for (int nf = 0; nf < 8; nf++) {
                mma16816(O[nf][0], O[nf][1], O[nf][2], O[nf][3],
                         pah[0], pah[1], pah[2], pah[3],
                         vh[cur][nf][0], vh[cur][nf][1]);
            }
        }
    }

    // ---- epilogue: normalize, store fp16 ----
    const float li0 = 1.f / l0r;
    const float li1 = 1.f / l1r;
    const size_t r0 = (size_t)(b * T_) + row_lo;
    const int colb = h * D_ + 2 * (lane & 3);
#pragma unroll
    for (int nf = 0; nf < 8; nf++) {
        const size_t c = colb + nf * 8;
        *reinterpret_cast<__half2*>(yh + r0 * C_ + c) =
            __floats2half2_rn(O[nf][0] * li0, O[nf][1] * li0);
        *reinterpret_cast<__half2*>(yh + (r0 + 8) * C_ + c) =
            __floats2half2_rn(O[nf][2] * li1, O[nf][3] * li1);
    }
}

// ---------------- launch ----------------
extern "C" void kernel_launch(void* const* d_in, const int* in_sizes, int n_in,
                              void* d_out, int out_size)
{
    const float* x      = (const float*)d_in[0];
    const float* w_attn = (const float*)d_in[1];
    const float* w_proj = (const float*)d_in[2];
    float* out = (float*)d_out;

    __half *xhi, *wahi, *wphi, *qkvh, *yhi;
    cudaGetSymbolAddress((void**)&xhi, g_xhi);
    cudaGetSymbolAddress((void**)&wahi, g_wahi);
    cudaGetSymbolAddress((void**)&wphi, g_wphi);
    cudaGetSymbolAddress((void**)&qkvh, g_qkvh);
    cudaGetSymbolAddress((void**)&yhi, g_yhi);

    cudaFuncSetAttribute(gemm_mma, cudaFuncAttributeMaxDynamicSharedMemorySize, GEMM_SMEM);
    cudaFuncSetAttribute(flash_attn_mma, cudaFuncAttributeMaxDynamicSharedMemorySize, AT_SMEM);

    {
        int n4 = M_ROWS * C_ / 4;
        trunc_f16<<<(n4 + 255) / 256, 256>>>((const float4*)x, (__half2*)xhi, n4);
    }
    {
        int n4 = C3_ * C_ / 4;
        trunc_f16<<<(n4 + 255) / 256, 256>>>((const float4*)w_attn, (__half2*)wahi, n4);
    }
    {
        int n4 = C_ * C_ / 4;
        trunc_f16<<<(n4 + 255) / 256, 256>>>((const float4*)w_proj, (__half2*)wphi, n4);
    }

    // 1) QKV = xh @ wah^T (1-term fp16) -> fp16
    {
        dim3 g(C3_ / 64, M_ROWS / 128);
        gemm_mma<<<g, 128, GEMM_SMEM>>>(xhi, wahi, nullptr, qkvh, 1, M_ROWS, C3_, C_);
    }
    // 2) tensor-core flash attention (1-term fp16) -> fp16
    {
        dim3 g(T_ / 64, H_, B_);
        flash_attn_mma<<<g, 128, AT_SMEM>>>(qkvh, yhi);
    }
    // 3) out = yh @ wph^T (1-term fp16, fp32 out)
    {
        dim3 g(C_ / 64, M_ROWS / 128);
        gemm_mma<<<g, 128, GEMM_SMEM>>>(yhi, wphi, out, nullptr, 0, M_ROWS, C_, C_);
    }
}